// round 6
// baseline (speedup 1.0000x reference)
#include <cuda_runtime.h>
#include <math.h>

// Problem constants
#define BATCH 8
#define FEAT  64
#define HW    262144             // 512*512
#define NSEG  33                 // ids 0..32 (0 = background)
#define NI    32

// Segment-max config
#define THREADS1 512             // 16 warps = 16 features per (b,fg) group
#define UNITPX   2048            // pixels per work unit
#define NTILE    (HW / UNITPX)   // 128 units per bfg
#define NU       (BATCH * 4 * NTILE)  // 4096 work units
#define NB       456             // 152 SMs * 3 CTAs

#define VEC_ELEMS (BATCH * NI * FEAT)   // 16384

// Per-(b,instance,feature) maxima as float bit patterns (nonneg -> int order ok).
__device__ int g_scratch[VEC_ELEMS];
__device__ unsigned int g_count;   // zero-init; tail resets to 0

extern __shared__ char smem_raw[];

// ---------------------------------------------------------------------------
// Fused kernel: persistent segment-max + last-block relation MLP.
//
// Segmax: 512 threads (16 warps); warp w <-> feature f = fg*16 + w.
// Private per-thread accumulators: s_acc[id*512 + tid] (thread-owned column,
// bank = tid%32, conflict-free). Mask ids are read straight from global
// (L1/L2-hit after the first warp touches them) — NO smem staging, NO
// __syncthreads anywhere in the main loop. Warps free-run; enc is streamed
// with __ldcs so masks stay cache-resident.
//
// MLP (collapsed — no nonlinearity between layers):
//   out[b,c,j,i] = sigmoid( v_i.(W1a W2) + v_j.(W1b W2) + (b1 W2 + b2) )
// run by the last block after a device-wide fence.
// ---------------------------------------------------------------------------
__global__ __launch_bounds__(THREADS1, 3)
void fused_kernel(const float* __restrict__ enc,
                  const int*   __restrict__ masks,
                  const float* __restrict__ w1,
                  const float* __restrict__ b1,
                  const float* __restrict__ w2,
                  const float* __restrict__ b2,
                  float*       __restrict__ out_vec,
                  float*       __restrict__ out_conn) {
    float* s_acc = (float*)smem_raw;        // 33*512 floats = 67584 B
    float* accT  = s_acc + threadIdx.x;     // this thread's private column

    const int tid  = threadIdx.x;
    const int lane = tid & 31;
    const int w    = tid >> 5;
    const int k    = blockIdx.x;

    const int s = (k * NU) / NB;
    const int e = ((k + 1) * NU) / NB;

    int cur = s >> 7;                       // bfg of first unit (128 units/bfg)
    int b   = cur >> 2;
    int f   = ((cur & 3) << 4) | w;

    // zero private column (thread-owned -> no sync needed)
    #pragma unroll
    for (int r = 0; r < NSEG; ++r) accT[r << 9] = 0.0f;

    for (int u = s; u < e; ++u) {
        const int bfg = u >> 7;
        if (bfg != cur) {
            // flush previous (b,fg): column is thread-private; warp-reduce per id
            #pragma unroll
            for (int id = 1; id < NSEG; ++id) {
                float v = accT[id << 9];
                #pragma unroll
                for (int off = 16; off; off >>= 1)
                    v = fmaxf(v, __shfl_xor_sync(0xffffffffu, v, off));
                if (lane == 0 && v > 0.0f)
                    atomicMax(&g_scratch[(b * NI + (id - 1)) * FEAT + f],
                              __float_as_int(v));
            }
            #pragma unroll
            for (int r = 0; r < NSEG; ++r) accT[r << 9] = 0.0f;
            cur = bfg;
            b   = bfg >> 2;
            f   = ((bfg & 3) << 4) | w;
        }

        // process unit u: warp covers 2048 px for its feature, 2 float4/thread/iter
        const int px = (u & 127) * UNITPX;
        const float4* src4 = (const float4*)enc
                           + (size_t)(b * FEAT + f) * (HW / 4) + (px >> 2);
        const int4*   id4  = (const int4*)(masks + (size_t)b * HW + px);

        #pragma unroll 2
        for (int g = 0; g < 8; ++g) {
            const int i0 = g * 64 + lane;
            const int i1 = i0 + 32;
            const float4 v0 = __ldcs(src4 + i0);   // streamed, evict-first
            const float4 v1 = __ldcs(src4 + i1);
            const int4 o0 = __ldg(id4 + i0);        // L1/L2-hit (shared by warps)
            const int4 o1 = __ldg(id4 + i1);

            accT[o0.x << 9] = fmaxf(accT[o0.x << 9], v0.x);
            accT[o0.y << 9] = fmaxf(accT[o0.y << 9], v0.y);
            accT[o0.z << 9] = fmaxf(accT[o0.z << 9], v0.z);
            accT[o0.w << 9] = fmaxf(accT[o0.w << 9], v0.w);
            accT[o1.x << 9] = fmaxf(accT[o1.x << 9], v1.x);
            accT[o1.y << 9] = fmaxf(accT[o1.y << 9], v1.y);
            accT[o1.z << 9] = fmaxf(accT[o1.z << 9], v1.z);
            accT[o1.w << 9] = fmaxf(accT[o1.w << 9], v1.w);
        }
    }

    // final flush
    #pragma unroll
    for (int id = 1; id < NSEG; ++id) {
        float v = accT[id << 9];
        #pragma unroll
        for (int off = 16; off; off >>= 1)
            v = fmaxf(v, __shfl_xor_sync(0xffffffffu, v, off));
        if (lane == 0 && v > 0.0f)
            atomicMax(&g_scratch[(b * NI + (id - 1)) * FEAT + f],
                      __float_as_int(v));
    }

    // ---- last-block-out runs the collapsed MLP ----
    __threadfence();
    __shared__ unsigned int s_rank;
    if (tid == 0) s_rank = atomicAdd(&g_count, 1u);
    __syncthreads();
    if (s_rank != NB - 1) return;
    __threadfence();   // acquire: all blocks' atomicMax results now visible

    // reuse dynamic smem (tail needs ~38 KB < 67584 B)
    float* s_w1 = (float*)smem_raw;        // 4096
    float* s_w2 = s_w1 + 4096;             // 128
    float* s_b1 = s_w2 + 128;              // 32
    float* s_b2 = s_b1 + 32;               // 4
    float* s_m1 = s_b2 + 4;                // 256: (W1a W2)[k][c]
    float* s_m2 = s_m1 + 256;              // 256: (W1b W2)[k][c]
    float* s_c0 = s_m2 + 256;              // 4
    float* s_v  = s_c0 + 4;                // 2 * 32*65 (padded)
    float* s_P  = s_v + 2 * 2080;          // 2 * 128
    float* s_Q  = s_P + 256;               // 2 * 128

    // stage weights (coalesced float4)
    ((float4*)s_w1)[tid]       = ((const float4*)w1)[tid];
    ((float4*)s_w1)[tid + 512] = ((const float4*)w1)[tid + 512];
    if (tid < 32) ((float4*)s_w2)[tid] = ((const float4*)w2)[tid];
    if (tid < 8)  ((float4*)s_b1)[tid] = ((const float4*)b1)[tid];
    if (tid < 4)  s_b2[tid] = b2[tid];
    __syncthreads();

    // fold: m1[k][c] = sum_m w1[k][m] w2[m][c]; m2 likewise for w1[64+k]
    if (tid < 256) {
        const int kk = tid >> 2, c = tid & 3;
        float a1 = 0.0f, a2 = 0.0f;
        #pragma unroll 8
        for (int m = 0; m < 32; ++m) {
            const float w2v = s_w2[m * 4 + c];
            a1 += s_w1[kk * 32 + m] * w2v;
            a2 += s_w1[(64 + kk) * 32 + m] * w2v;
        }
        s_m1[tid] = a1;
        s_m2[tid] = a2;
    } else if (tid < 260) {
        const int c = tid - 256;
        float a = s_b2[c];
        #pragma unroll 8
        for (int m = 0; m < 32; ++m) a += s_b1[m] * s_w2[m * 4 + c];
        s_c0[c] = a;
    }
    __syncthreads();

    // two batches per round
    for (int bb = 0; bb < BATCH; bb += 2) {
        for (int t = tid; t < 2 * NI * FEAT; t += THREADS1) {
            const int bloc = t >> 11;
            const int loc  = t & 2047;
            const int gidx = (bb + bloc) * NI * FEAT + loc;
            const float vv = __int_as_float(g_scratch[gidx]);
            s_v[bloc * 2080 + (loc >> 6) * 65 + (loc & 63)] = vv;
            out_vec[gidx]   = vv;
            g_scratch[gidx] = 0;
        }
        __syncthreads();

        {   // P[i][c] = v_i . m1_c ; Q[j][c] = v_j . m2_c   (512 threads exactly)
            const int bloc = tid >> 8;
            const int t2   = tid & 255;
            const int isQ  = t2 >> 7;
            const int idx  = t2 & 127;
            const int r = idx >> 2, c = idx & 3;
            const float* vm = s_v + bloc * 2080 + r * 65;
            const float* mm = isQ ? s_m2 : s_m1;
            float a = 0.0f;
            #pragma unroll 8
            for (int kk = 0; kk < FEAT; ++kk) a += vm[kk] * mm[kk * 4 + c];
            if (isQ) s_Q[bloc * 128 + idx] = a;
            else     s_P[bloc * 128 + idx] = a;
        }
        __syncthreads();

        #pragma unroll
        for (int rr = 0; rr < 16; ++rr) {
            const int o     = rr * THREADS1 + tid;   // 0..8191
            const int bloc  = o >> 12;
            const int oo    = o & 4095;              // c*1024 + j*32 + i
            const int c  = oo >> 10;
            const int j  = (oo >> 5) & 31;
            const int i  = oo & 31;
            const float t = s_P[bloc * 128 + i * 4 + c]
                          + s_Q[bloc * 128 + j * 4 + c] + s_c0[c];
            out_conn[(size_t)(bb + bloc) * 4096 + oo] = 1.0f / (1.0f + __expf(-t));
        }
        __syncthreads();
    }

    if (tid == 0) g_count = 0;   // restore state for next identical call
}

// ---------------------------------------------------------------------------
// Launch
// ---------------------------------------------------------------------------
extern "C" void kernel_launch(void* const* d_in, const int* in_sizes, int n_in,
                              void* d_out, int out_size) {
    const float* enc   = (const float*)d_in[0];
    const int*   masks = (const int*)d_in[1];
    const float* w1    = (const float*)d_in[2];
    const float* b1    = (const float*)d_in[3];
    const float* w2    = (const float*)d_in[4];
    const float* b2    = (const float*)d_in[5];

    float* out_vec  = (float*)d_out;
    float* out_conn = out_vec + VEC_ELEMS;

    static bool attr_set = false;
    const int smem_bytes = NSEG * THREADS1 * 4;   // 67584
    if (!attr_set) {
        cudaFuncSetAttribute(fused_kernel,
                             cudaFuncAttributeMaxDynamicSharedMemorySize, smem_bytes);
        attr_set = true;
    }

    fused_kernel<<<NB, THREADS1, smem_bytes>>>(enc, masks, w1, b1, w2, b2,
                                               out_vec, out_conn);
}

// round 7
// speedup vs baseline: 1.2099x; 1.2099x over previous
#include <cuda_runtime.h>
#include <math.h>

// Problem constants
#define BATCH 8
#define FEAT  64
#define HW    262144             // 512*512
#define NSEG  33                 // ids 0..32 (0 = background)
#define NI    32

// Segment-max config (R2-proven loop)
#define THREADS1 512             // 16 warps = 16 features per (b,fg) group
#define TILEPX   2048            // pixels per work unit
#define NTILE    (HW / TILEPX)   // 128
#define NU       (BATCH * 4 * NTILE)  // 4096 work units
#define NB       456             // 152 SMs * 3 CTAs, exact single wave

#define VEC_ELEMS (BATCH * NI * FEAT)   // 16384

// Per-(b,instance,feature) maxima as float bit patterns (nonneg -> int order ok).
// Statically zeroed; mlp kernel re-zeroes after consuming, so every call sees
// identical initial state.
__device__ int g_scratch[VEC_ELEMS];

extern __shared__ char smem_raw[];

// ---------------------------------------------------------------------------
// Kernel 1: persistent segment-max (R2 structure).
// Block = 512 threads (16 warps); warp w <-> feature f = fg*16 + w.
// Per-thread private accumulators in smem: s_acc[id*512 + tid] (bank=tid%32,
// always conflict-free). Ids staged in smem premultiplied by 512.
// ---------------------------------------------------------------------------
__global__ __launch_bounds__(THREADS1, 3)
void segmax_kernel(const float* __restrict__ enc,
                   const int*   __restrict__ masks) {
    float* s_acc = (float*)smem_raw;                          // 33*512 floats = 67584 B
    int*   s_ids = (int*)(smem_raw + NSEG * THREADS1 * 4);    // 2048 ints   =  8192 B

    const int tid  = threadIdx.x;
    const int lane = tid & 31;
    const int w    = tid >> 5;
    const int k    = blockIdx.x;

    const int s = (k * NU) / NB;
    const int e = ((k + 1) * NU) / NB;

    int cur = -1;
    int b = 0, f = 0;

    for (int u = s; u < e; ++u) {
        const int bfg = u >> 7;             // u / NTILE
        if (bfg != cur) {
            if (cur >= 0) {
                // flush: column tid is private to this thread; warp-reduce per id
                #pragma unroll
                for (int id = 1; id < NSEG; ++id) {
                    float v = s_acc[(id << 9) + tid];
                    #pragma unroll
                    for (int off = 16; off; off >>= 1)
                        v = fmaxf(v, __shfl_xor_sync(0xffffffffu, v, off));
                    if (lane == 0 && v > 0.0f)
                        atomicMax(&g_scratch[((b * NI) + (id - 1)) * FEAT + f],
                                  __float_as_int(v));
                }
            }
            #pragma unroll
            for (int r = 0; r < NSEG; ++r) s_acc[(r << 9) + tid] = 0.0f;
            cur = bfg;
            b = bfg >> 2;
            f = ((bfg & 3) << 4) | w;
        }
        const int tile = u & (NTILE - 1);

        // Stage mask ids for this tile (premultiplied by 512 = row stride).
        __syncthreads();   // prior tile's s_ids consumers are done
        {
            const int4 m = ((const int4*)(masks + (size_t)b * HW + tile * TILEPX))[tid];
            ((int4*)s_ids)[tid] = make_int4(m.x << 9, m.y << 9, m.z << 9, m.w << 9);
        }
        __syncthreads();

        const float4* src4 = (const float4*)enc
                           + (size_t)(b * FEAT + f) * (HW / 4)
                           + tile * (TILEPX / 4);
        const int4* id4 = (const int4*)s_ids;

        #pragma unroll 4
        for (int g = 0; g < TILEPX / 4 / 32; ++g) {   // 16 iterations
            const int idx = g * 32 + lane;
            const float4 v = src4[idx];
            const int4  o = id4[idx];
            float a;
            a = s_acc[o.x + tid]; if (v.x > a) s_acc[o.x + tid] = v.x;
            a = s_acc[o.y + tid]; if (v.y > a) s_acc[o.y + tid] = v.y;
            a = s_acc[o.z + tid]; if (v.z > a) s_acc[o.z + tid] = v.z;
            a = s_acc[o.w + tid]; if (v.w > a) s_acc[o.w + tid] = v.w;
        }
    }

    // final flush
    #pragma unroll
    for (int id = 1; id < NSEG; ++id) {
        float v = s_acc[(id << 9) + tid];
        #pragma unroll
        for (int off = 16; off; off >>= 1)
            v = fmaxf(v, __shfl_xor_sync(0xffffffffu, v, off));
        if (lane == 0 && v > 0.0f)
            atomicMax(&g_scratch[((b * NI) + (id - 1)) * FEAT + f],
                      __float_as_int(v));
    }
}

// ---------------------------------------------------------------------------
// Kernel 2: collapsed relation MLP (no nonlinearity between layers):
//   out[b,c,j,i] = sigmoid( v_i.(W1a W2) + v_j.(W1b W2) + (b1 W2 + b2) )
// One block per batch. Also copies vectors to d_out and re-zeroes scratch.
// ---------------------------------------------------------------------------
#define TH2 256

__global__ __launch_bounds__(TH2)
void mlp_kernel(const float* __restrict__ w1,
                const float* __restrict__ b1,
                const float* __restrict__ w2,
                const float* __restrict__ b2,
                float* __restrict__ out_vec,
                float* __restrict__ out_conn) {
    __shared__ float s_w1[128 * 32];   // 16 KB
    __shared__ float s_w2[32 * 4];
    __shared__ float s_b1[32];
    __shared__ float s_b2[4];
    __shared__ float s_m1[FEAT * 4];   // (W1a W2)[k][c]
    __shared__ float s_m2[FEAT * 4];   // (W1b W2)[k][c]
    __shared__ float s_c0[4];
    __shared__ float s_v[NI * 65];     // padded stride 65
    __shared__ float s_P[NI * 4];
    __shared__ float s_Q[NI * 4];

    const int b   = blockIdx.x;
    const int tid = threadIdx.x;

    // stage weights (coalesced float4) + this batch's vectors
    #pragma unroll
    for (int t = 0; t < 4; ++t)
        ((float4*)s_w1)[tid + t * TH2] = ((const float4*)w1)[tid + t * TH2];
    if (tid < 32) ((float4*)s_w2)[tid] = ((const float4*)w2)[tid];
    if (tid < 8)  ((float4*)s_b1)[tid] = ((const float4*)b1)[tid];
    if (tid < 4)  s_b2[tid] = b2[tid];

    for (int t = tid; t < NI * FEAT; t += TH2) {
        const int gidx = b * NI * FEAT + t;
        const float vv = __int_as_float(g_scratch[gidx]);
        s_v[(t >> 6) * 65 + (t & 63)] = vv;
        out_vec[gidx]   = vv;
        g_scratch[gidx] = 0;           // restore zero state for next call
    }
    __syncthreads();

    // fold: m1[k][c] = sum_m w1[k][m] w2[m][c]; m2 likewise for w1[64+k]
    {
        const int kk = tid >> 2, c = tid & 3;
        float a1 = 0.0f, a2 = 0.0f;
        #pragma unroll 8
        for (int m = 0; m < 32; ++m) {
            const float w2v = s_w2[m * 4 + c];
            a1 += s_w1[kk * 32 + m] * w2v;
            a2 += s_w1[(64 + kk) * 32 + m] * w2v;
        }
        s_m1[tid] = a1;
        s_m2[tid] = a2;
        if (tid < 4) {
            float a = s_b2[tid];
            #pragma unroll 8
            for (int m = 0; m < 32; ++m) a += s_b1[m] * s_w2[m * 4 + tid];
            s_c0[tid] = a;
        }
    }
    __syncthreads();

    // P[i][c] = v_i . m1_c ; Q[j][c] = v_j . m2_c
    {
        const int isQ = tid >> 7;
        const int idx = tid & 127;
        const int r = idx >> 2, c = idx & 3;
        const float* vm = s_v + r * 65;
        const float* mm = isQ ? s_m2 : s_m1;
        float a = 0.0f;
        #pragma unroll 8
        for (int kk = 0; kk < FEAT; ++kk) a += vm[kk] * mm[kk * 4 + c];
        if (isQ) s_Q[idx] = a;
        else     s_P[idx] = a;
    }
    __syncthreads();

    // out[b, c, j, i] = sigmoid(P[i][c] + Q[j][c] + c0[c])
    #pragma unroll
    for (int rr = 0; rr < 16; ++rr) {
        const int o = rr * TH2 + tid;        // o = c*1024 + j*32 + i
        const int c = o >> 10;
        const int j = (o >> 5) & 31;
        const int i = o & 31;
        const float t = s_P[i * 4 + c] + s_Q[j * 4 + c] + s_c0[c];
        out_conn[(size_t)b * 4096 + o] = 1.0f / (1.0f + __expf(-t));
    }
}

// ---------------------------------------------------------------------------
// Launch
// ---------------------------------------------------------------------------
extern "C" void kernel_launch(void* const* d_in, const int* in_sizes, int n_in,
                              void* d_out, int out_size) {
    const float* enc   = (const float*)d_in[0];
    const int*   masks = (const int*)d_in[1];
    const float* w1    = (const float*)d_in[2];
    const float* b1    = (const float*)d_in[3];
    const float* w2    = (const float*)d_in[4];
    const float* b2    = (const float*)d_in[5];

    float* out_vec  = (float*)d_out;
    float* out_conn = out_vec + VEC_ELEMS;

    static bool attr_set = false;
    const int smem_bytes = NSEG * THREADS1 * 4 + TILEPX * 4;  // 75776
    if (!attr_set) {
        cudaFuncSetAttribute(segmax_kernel,
                             cudaFuncAttributeMaxDynamicSharedMemorySize, smem_bytes);
        attr_set = true;
    }

    segmax_kernel<<<NB, THREADS1, smem_bytes>>>(enc, masks);
    mlp_kernel<<<BATCH, TH2>>>(w1, b1, w2, b2, out_vec, out_conn);
}

// round 8
// speedup vs baseline: 1.2215x; 1.0096x over previous
#include <cuda_runtime.h>
#include <math.h>

// Problem constants
#define BATCH 8
#define FEAT  64
#define HW    262144             // 512*512
#define NSEG  33                 // ids 0..32 (0 = background)
#define NI    32

// Segment-max config (R2/R7-proven loop — DO NOT TOUCH)
#define THREADS1 512             // 16 warps = 16 features per (b,fg) group
#define TILEPX   2048            // pixels per work unit
#define NTILE    (HW / TILEPX)   // 128
#define NU       (BATCH * 4 * NTILE)  // 4096 work units
#define NB       456             // 152 SMs * 3 CTAs, exact single wave

#define VEC_ELEMS (BATCH * NI * FEAT)   // 16384

// Per-(b,instance,feature) maxima as float bit patterns (nonneg -> int order ok).
// Statically zeroed; mlp kernel re-zeroes after consuming, so every call sees
// identical initial state.
__device__ int g_scratch[VEC_ELEMS];
__device__ unsigned int g_cnt[BATCH];   // per-batch arrival tickets (zero-init, self-resetting)

extern __shared__ char smem_raw[];

// ---------------------------------------------------------------------------
// Kernel 1: persistent segment-max (R2 structure, R7-measured ~99.7us).
// ---------------------------------------------------------------------------
__global__ __launch_bounds__(THREADS1, 3)
void segmax_kernel(const float* __restrict__ enc,
                   const int*   __restrict__ masks) {
    float* s_acc = (float*)smem_raw;                          // 33*512 floats = 67584 B
    int*   s_ids = (int*)(smem_raw + NSEG * THREADS1 * 4);    // 2048 ints   =  8192 B

    const int tid  = threadIdx.x;
    const int lane = tid & 31;
    const int w    = tid >> 5;
    const int k    = blockIdx.x;

    const int s = (k * NU) / NB;
    const int e = ((k + 1) * NU) / NB;

    int cur = -1;
    int b = 0, f = 0;

    for (int u = s; u < e; ++u) {
        const int bfg = u >> 7;             // u / NTILE
        if (bfg != cur) {
            if (cur >= 0) {
                // flush: column tid is private to this thread; warp-reduce per id
                #pragma unroll
                for (int id = 1; id < NSEG; ++id) {
                    float v = s_acc[(id << 9) + tid];
                    #pragma unroll
                    for (int off = 16; off; off >>= 1)
                        v = fmaxf(v, __shfl_xor_sync(0xffffffffu, v, off));
                    if (lane == 0 && v > 0.0f)
                        atomicMax(&g_scratch[((b * NI) + (id - 1)) * FEAT + f],
                                  __float_as_int(v));
                }
            }
            #pragma unroll
            for (int r = 0; r < NSEG; ++r) s_acc[(r << 9) + tid] = 0.0f;
            cur = bfg;
            b = bfg >> 2;
            f = ((bfg & 3) << 4) | w;
        }
        const int tile = u & (NTILE - 1);

        // Stage mask ids for this tile (premultiplied by 512 = row stride).
        __syncthreads();   // prior tile's s_ids consumers are done
        {
            const int4 m = ((const int4*)(masks + (size_t)b * HW + tile * TILEPX))[tid];
            ((int4*)s_ids)[tid] = make_int4(m.x << 9, m.y << 9, m.z << 9, m.w << 9);
        }
        __syncthreads();

        const float4* src4 = (const float4*)enc
                           + (size_t)(b * FEAT + f) * (HW / 4)
                           + tile * (TILEPX / 4);
        const int4* id4 = (const int4*)s_ids;

        #pragma unroll 4
        for (int g = 0; g < TILEPX / 4 / 32; ++g) {   // 16 iterations
            const int idx = g * 32 + lane;
            const float4 v = src4[idx];
            const int4  o = id4[idx];
            float a;
            a = s_acc[o.x + tid]; if (v.x > a) s_acc[o.x + tid] = v.x;
            a = s_acc[o.y + tid]; if (v.y > a) s_acc[o.y + tid] = v.y;
            a = s_acc[o.z + tid]; if (v.z > a) s_acc[o.z + tid] = v.z;
            a = s_acc[o.w + tid]; if (v.w > a) s_acc[o.w + tid] = v.w;
        }
    }

    // final flush
    #pragma unroll
    for (int id = 1; id < NSEG; ++id) {
        float v = s_acc[(id << 9) + tid];
        #pragma unroll
        for (int off = 16; off; off >>= 1)
            v = fmaxf(v, __shfl_xor_sync(0xffffffffu, v, off));
        if (lane == 0 && v > 0.0f)
            atomicMax(&g_scratch[((b * NI) + (id - 1)) * FEAT + f],
                      __float_as_int(v));
    }
}

// ---------------------------------------------------------------------------
// Kernel 2: collapsed relation MLP, spread over 152 blocks (19 per batch)
// to clear the low-grid SM issue throttle.
//   out[b,c,j,i] = sigmoid( v_i.(W1a W2) + v_j.(W1b W2) + (b1 W2 + b2) )
// Every block of a batch redundantly folds weights and computes P/Q (tiny,
// L2-served), then writes its own 216-element output slice. The 19th block
// to arrive (atomic ticket) writes out_vec and re-zeroes that batch's
// scratch slice + ticket, restoring initial state for the next replay.
// ---------------------------------------------------------------------------
#define TH2    256
#define SLICES 19
#define OSLICE 216              // ceil(4096 / 19)

__global__ __launch_bounds__(TH2)
void mlp_kernel(const float* __restrict__ w1,
                const float* __restrict__ b1,
                const float* __restrict__ w2,
                const float* __restrict__ b2,
                float* __restrict__ out_vec,
                float* __restrict__ out_conn) {
    __shared__ float s_w1[128 * 32];   // 16 KB
    __shared__ float s_w2[32 * 4];
    __shared__ float s_b1[32];
    __shared__ float s_b2[4];
    __shared__ float s_m1[FEAT * 4];   // (W1a W2)[k][c]
    __shared__ float s_m2[FEAT * 4];   // (W1b W2)[k][c]
    __shared__ float s_c0[4];
    __shared__ float s_v[NI * 65];     // padded stride 65
    __shared__ float s_P[NI * 4];
    __shared__ float s_Q[NI * 4];
    __shared__ unsigned int s_rank;

    const int b   = blockIdx.x / SLICES;
    const int sl  = blockIdx.x % SLICES;
    const int tid = threadIdx.x;

    // stage weights (coalesced float4) + this batch's vectors
    #pragma unroll
    for (int t = 0; t < 4; ++t)
        ((float4*)s_w1)[tid + t * TH2] = ((const float4*)w1)[tid + t * TH2];
    if (tid < 32) ((float4*)s_w2)[tid] = ((const float4*)w2)[tid];
    if (tid < 8)  ((float4*)s_b1)[tid] = ((const float4*)b1)[tid];
    if (tid < 4)  s_b2[tid] = b2[tid];

    #pragma unroll
    for (int t = tid; t < NI * FEAT; t += TH2)
        s_v[(t >> 6) * 65 + (t & 63)] = __int_as_float(g_scratch[b * NI * FEAT + t]);
    __syncthreads();

    // fold: m1[k][c] = sum_m w1[k][m] w2[m][c]; m2 likewise for w1[64+k]
    {
        const int kk = tid >> 2, c = tid & 3;
        float a1 = 0.0f, a2 = 0.0f;
        #pragma unroll 8
        for (int m = 0; m < 32; ++m) {
            const float w2v = s_w2[m * 4 + c];
            a1 += s_w1[kk * 32 + m] * w2v;
            a2 += s_w1[(64 + kk) * 32 + m] * w2v;
        }
        s_m1[tid] = a1;
        s_m2[tid] = a2;
        if (tid < 4) {
            float a = s_b2[tid];
            #pragma unroll 8
            for (int m = 0; m < 32; ++m) a += s_b1[m] * s_w2[m * 4 + tid];
            s_c0[tid] = a;
        }
    }
    __syncthreads();

    // P[i][c] = v_i . m1_c ; Q[j][c] = v_j . m2_c
    {
        const int isQ = tid >> 7;
        const int idx = tid & 127;
        const int r = idx >> 2, c = idx & 3;
        const float* vm = s_v + r * 65;
        const float* mm = isQ ? s_m2 : s_m1;
        float a = 0.0f;
        #pragma unroll 8
        for (int kk = 0; kk < FEAT; ++kk) a += vm[kk] * mm[kk * 4 + c];
        if (isQ) s_Q[idx] = a;
        else     s_P[idx] = a;
    }
    __syncthreads();

    // this block's output slice: o in [sl*216, min(4096, sl*216+216))
    {
        const int o = sl * OSLICE + tid;
        if (tid < OSLICE && o < 4096) {      // o = c*1024 + j*32 + i
            const int c = o >> 10;
            const int j = (o >> 5) & 31;
            const int i = o & 31;
            const float t = s_P[i * 4 + c] + s_Q[j * 4 + c] + s_c0[c];
            out_conn[(size_t)b * 4096 + o] = 1.0f / (1.0f + __expf(-t));
        }
    }

    // last block of this batch writes vectors + re-zeroes scratch & ticket.
    // All 19 blocks' g_scratch reads completed before their arrival.
    __threadfence();
    if (tid == 0) s_rank = atomicAdd(&g_cnt[b], 1u);
    __syncthreads();
    if (s_rank == SLICES - 1) {
        #pragma unroll
        for (int t = tid; t < NI * FEAT; t += TH2) {
            const int gidx = b * NI * FEAT + t;
            out_vec[gidx]   = s_v[(t >> 6) * 65 + (t & 63)];
            g_scratch[gidx] = 0;
        }
        if (tid == 0) g_cnt[b] = 0;
    }
}

// ---------------------------------------------------------------------------
// Launch
// ---------------------------------------------------------------------------
extern "C" void kernel_launch(void* const* d_in, const int* in_sizes, int n_in,
                              void* d_out, int out_size) {
    const float* enc   = (const float*)d_in[0];
    const int*   masks = (const int*)d_in[1];
    const float* w1    = (const float*)d_in[2];
    const float* b1    = (const float*)d_in[3];
    const float* w2    = (const float*)d_in[4];
    const float* b2    = (const float*)d_in[5];

    float* out_vec  = (float*)d_out;
    float* out_conn = out_vec + VEC_ELEMS;

    static bool attr_set = false;
    const int smem_bytes = NSEG * THREADS1 * 4 + TILEPX * 4;  // 75776
    if (!attr_set) {
        cudaFuncSetAttribute(segmax_kernel,
                             cudaFuncAttributeMaxDynamicSharedMemorySize, smem_bytes);
        attr_set = true;
    }

    segmax_kernel<<<NB, THREADS1, smem_bytes>>>(enc, masks);
    mlp_kernel<<<BATCH * SLICES, TH2>>>(w1, b1, w2, b2, out_vec, out_conn);
}

// round 9
// speedup vs baseline: 1.2366x; 1.0123x over previous
#include <cuda_runtime.h>
#include <math.h>

// Problem constants
#define BATCH 8
#define FEAT  64
#define HW    262144             // 512*512
#define NSEG  33                 // ids 0..32 (0 = background)
#define NI    32

// Segment-max config (R2/R7-proven loop — DO NOT TOUCH)
#define THREADS1 512             // 16 warps = 16 features per (b,fg) group
#define TILEPX   2048            // pixels per work unit
#define NTILE    (HW / TILEPX)   // 128
#define NU       (BATCH * 4 * NTILE)  // 4096 work units
#define NB       456             // 152 SMs * 3 CTAs, exact single wave

#define VEC_ELEMS (BATCH * NI * FEAT)   // 16384

// Per-(b,instance,feature) maxima as float bit patterns (nonneg -> int order ok).
// Statically zeroed; mlp kernel re-zeroes after consuming, so every call sees
// identical initial state.
__device__ int g_scratch[VEC_ELEMS];
__device__ unsigned int g_cnt[BATCH];   // per-batch arrival tickets (zero-init, self-resetting)

extern __shared__ char smem_raw[];

// ---------------------------------------------------------------------------
// Kernel 1: persistent segment-max (R2 structure, R7-measured ~99.7us).
// Ends with the PDL completion trigger (after all scratch writes).
// ---------------------------------------------------------------------------
__global__ __launch_bounds__(THREADS1, 3)
void segmax_kernel(const float* __restrict__ enc,
                   const int*   __restrict__ masks) {
    float* s_acc = (float*)smem_raw;                          // 33*512 floats = 67584 B
    int*   s_ids = (int*)(smem_raw + NSEG * THREADS1 * 4);    // 2048 ints   =  8192 B

    const int tid  = threadIdx.x;
    const int lane = tid & 31;
    const int w    = tid >> 5;
    const int k    = blockIdx.x;

    const int s = (k * NU) / NB;
    const int e = ((k + 1) * NU) / NB;

    int cur = -1;
    int b = 0, f = 0;

    for (int u = s; u < e; ++u) {
        const int bfg = u >> 7;             // u / NTILE
        if (bfg != cur) {
            if (cur >= 0) {
                // flush: column tid is private to this thread; warp-reduce per id
                #pragma unroll
                for (int id = 1; id < NSEG; ++id) {
                    float v = s_acc[(id << 9) + tid];
                    #pragma unroll
                    for (int off = 16; off; off >>= 1)
                        v = fmaxf(v, __shfl_xor_sync(0xffffffffu, v, off));
                    if (lane == 0 && v > 0.0f)
                        atomicMax(&g_scratch[((b * NI) + (id - 1)) * FEAT + f],
                                  __float_as_int(v));
                }
            }
            #pragma unroll
            for (int r = 0; r < NSEG; ++r) s_acc[(r << 9) + tid] = 0.0f;
            cur = bfg;
            b = bfg >> 2;
            f = ((bfg & 3) << 4) | w;
        }
        const int tile = u & (NTILE - 1);

        // Stage mask ids for this tile (premultiplied by 512 = row stride).
        __syncthreads();   // prior tile's s_ids consumers are done
        {
            const int4 m = ((const int4*)(masks + (size_t)b * HW + tile * TILEPX))[tid];
            ((int4*)s_ids)[tid] = make_int4(m.x << 9, m.y << 9, m.z << 9, m.w << 9);
        }
        __syncthreads();

        const float4* src4 = (const float4*)enc
                           + (size_t)(b * FEAT + f) * (HW / 4)
                           + tile * (TILEPX / 4);
        const int4* id4 = (const int4*)s_ids;

        #pragma unroll 4
        for (int g = 0; g < TILEPX / 4 / 32; ++g) {   // 16 iterations
            const int idx = g * 32 + lane;
            const float4 v = src4[idx];
            const int4  o = id4[idx];
            float a;
            a = s_acc[o.x + tid]; if (v.x > a) s_acc[o.x + tid] = v.x;
            a = s_acc[o.y + tid]; if (v.y > a) s_acc[o.y + tid] = v.y;
            a = s_acc[o.z + tid]; if (v.z > a) s_acc[o.z + tid] = v.z;
            a = s_acc[o.w + tid]; if (v.w > a) s_acc[o.w + tid] = v.w;
        }
    }

    // final flush
    #pragma unroll
    for (int id = 1; id < NSEG; ++id) {
        float v = s_acc[(id << 9) + tid];
        #pragma unroll
        for (int off = 16; off; off >>= 1)
            v = fmaxf(v, __shfl_xor_sync(0xffffffffu, v, off));
        if (lane == 0 && v > 0.0f)
            atomicMax(&g_scratch[((b * NI) + (id - 1)) * FEAT + f],
                      __float_as_int(v));
    }

    // All this CTA's scratch writes are done -> allow dependent grid.
#if __CUDA_ARCH__ >= 900
    cudaTriggerProgrammaticLaunchCompletion();
#endif
}

// ---------------------------------------------------------------------------
// Kernel 2: collapsed relation MLP, 152 blocks (19 per batch), launched with
// PDL so its weight-staging + fold prologue overlaps segmax's tail.
//   out[b,c,j,i] = sigmoid( v_i.(W1a W2) + v_j.(W1b W2) + (b1 W2 + b2) )
// ---------------------------------------------------------------------------
#define TH2    256
#define SLICES 19
#define OSLICE 216              // ceil(4096 / 19)

__global__ __launch_bounds__(TH2)
void mlp_kernel(const float* __restrict__ w1,
                const float* __restrict__ b1,
                const float* __restrict__ w2,
                const float* __restrict__ b2,
                float* __restrict__ out_vec,
                float* __restrict__ out_conn) {
    __shared__ float s_w1[128 * 32];   // 16 KB
    __shared__ float s_w2[32 * 4];
    __shared__ float s_b1[32];
    __shared__ float s_b2[4];
    __shared__ float s_m1[FEAT * 4];   // (W1a W2)[k][c]
    __shared__ float s_m2[FEAT * 4];   // (W1b W2)[k][c]
    __shared__ float s_c0[4];
    __shared__ float s_v[NI * 65];     // padded stride 65
    __shared__ float s_P[NI * 4];
    __shared__ float s_Q[NI * 4];
    __shared__ unsigned int s_rank;

    const int b   = blockIdx.x / SLICES;
    const int sl  = blockIdx.x % SLICES;
    const int tid = threadIdx.x;

    // ---- PDL prologue: depends ONLY on weight inputs (not on segmax) ----
    #pragma unroll
    for (int t = 0; t < 4; ++t)
        ((float4*)s_w1)[tid + t * TH2] = ((const float4*)w1)[tid + t * TH2];
    if (tid < 32) ((float4*)s_w2)[tid] = ((const float4*)w2)[tid];
    if (tid < 8)  ((float4*)s_b1)[tid] = ((const float4*)b1)[tid];
    if (tid < 4)  s_b2[tid] = b2[tid];
    __syncthreads();

    // fold: m1[k][c] = sum_m w1[k][m] w2[m][c]; m2 likewise for w1[64+k]
    {
        const int kk = tid >> 2, c = tid & 3;
        float a1 = 0.0f, a2 = 0.0f;
        #pragma unroll 8
        for (int m = 0; m < 32; ++m) {
            const float w2v = s_w2[m * 4 + c];
            a1 += s_w1[kk * 32 + m] * w2v;
            a2 += s_w1[(64 + kk) * 32 + m] * w2v;
        }
        s_m1[tid] = a1;
        s_m2[tid] = a2;
        if (tid < 4) {
            float a = s_b2[tid];
            #pragma unroll 8
            for (int m = 0; m < 32; ++m) a += s_b1[m] * s_w2[m * 4 + tid];
            s_c0[tid] = a;
        }
    }

    // ---- wait for segmax's scratch writes to be visible ----
#if __CUDA_ARCH__ >= 900
    cudaGridDependencySynchronize();
#endif

    #pragma unroll
    for (int t = tid; t < NI * FEAT; t += TH2)
        s_v[(t >> 6) * 65 + (t & 63)] = __int_as_float(g_scratch[b * NI * FEAT + t]);
    __syncthreads();

    // P[i][c] = v_i . m1_c ; Q[j][c] = v_j . m2_c
    {
        const int isQ = tid >> 7;
        const int idx = tid & 127;
        const int r = idx >> 2, c = idx & 3;
        const float* vm = s_v + r * 65;
        const float* mm = isQ ? s_m2 : s_m1;
        float a = 0.0f;
        #pragma unroll 8
        for (int kk = 0; kk < FEAT; ++kk) a += vm[kk] * mm[kk * 4 + c];
        if (isQ) s_Q[idx] = a;
        else     s_P[idx] = a;
    }
    __syncthreads();

    // this block's output slice: o in [sl*216, min(4096, sl*216+216))
    {
        const int o = sl * OSLICE + tid;
        if (tid < OSLICE && o < 4096) {      // o = c*1024 + j*32 + i
            const int c = o >> 10;
            const int j = (o >> 5) & 31;
            const int i = o & 31;
            const float t = s_P[i * 4 + c] + s_Q[j * 4 + c] + s_c0[c];
            out_conn[(size_t)b * 4096 + o] = 1.0f / (1.0f + __expf(-t));
        }
    }

    // last block of this batch writes vectors + re-zeroes scratch & ticket.
    __threadfence();
    if (tid == 0) s_rank = atomicAdd(&g_cnt[b], 1u);
    __syncthreads();
    if (s_rank == SLICES - 1) {
        #pragma unroll
        for (int t = tid; t < NI * FEAT; t += TH2) {
            const int gidx = b * NI * FEAT + t;
            out_vec[gidx]   = s_v[(t >> 6) * 65 + (t & 63)];
            g_scratch[gidx] = 0;
        }
        if (tid == 0) g_cnt[b] = 0;
    }
}

// ---------------------------------------------------------------------------
// Launch: segmax, then mlp with programmatic stream serialization (PDL).
// ---------------------------------------------------------------------------
extern "C" void kernel_launch(void* const* d_in, const int* in_sizes, int n_in,
                              void* d_out, int out_size) {
    const float* enc   = (const float*)d_in[0];
    const int*   masks = (const int*)d_in[1];
    const float* w1    = (const float*)d_in[2];
    const float* b1    = (const float*)d_in[3];
    const float* w2    = (const float*)d_in[4];
    const float* b2    = (const float*)d_in[5];

    float* out_vec  = (float*)d_out;
    float* out_conn = out_vec + VEC_ELEMS;

    static bool attr_set = false;
    const int smem_bytes = NSEG * THREADS1 * 4 + TILEPX * 4;  // 75776
    if (!attr_set) {
        cudaFuncSetAttribute(segmax_kernel,
                             cudaFuncAttributeMaxDynamicSharedMemorySize, smem_bytes);
        attr_set = true;
    }

    segmax_kernel<<<NB, THREADS1, smem_bytes>>>(enc, masks);

    // PDL launch of the mlp: may begin while segmax drains; it gates its
    // g_scratch reads on cudaGridDependencySynchronize().
    cudaLaunchConfig_t cfg = {};
    cfg.gridDim  = dim3(BATCH * SLICES, 1, 1);
    cfg.blockDim = dim3(TH2, 1, 1);
    cfg.dynamicSmemBytes = 0;
    cudaLaunchAttribute attrs[1];
    attrs[0].id = cudaLaunchAttributeProgrammaticStreamSerialization;
    attrs[0].val.programmaticStreamSerializationAllowed = 1;
    cfg.attrs = attrs;
    cfg.numAttrs = 1;
    cudaLaunchKernelEx(&cfg, mlp_kernel, w1, b1, w2, b2, out_vec, out_conn);
}